// round 13
// baseline (speedup 1.0000x reference)
#include <cuda_runtime.h>
#include <cuda_fp16.h>
#include <cstdint>

// Problem constants
#define B_ROWS 65536
#define D_DIM  512
#define C_DIM  101
#define E_DIM  8
#define H_DIM  256

#define THREADS 256
#define M_TILE 32
#define KC     32        // GEMM1 K-chunk (per-warp private staging)
#define NCH    16        // 512/32 chunks
#define XP     520       // fp16 pitch xhi (1040B; %128B=16 -> LDSM conflict-free)
#define HGP    264       // fp16 pitch hidden tile (528B; %128=16)
#define B1PITCH 80       // bytes/row, W1 ring (32 halfs + pad)
#define B2PITCH 144      // bytes/row, W2 ring (64 halfs + pad; %128=16)
#define BUF_SZ 2560      // one ring buffer: 32 rows x 80B (W2: 16 x 144 = 2304 fits)

// Shared memory layout (bytes) — 112288 total -> 2 CTAs/SM
#define SM_XHI 0         // 32*520*2 = 33280
#define SM_WB  33280     // 8 warps x 2 bufs x 2560 = 40960
#define SM_HG0 74240     // 32*264*2 = 16896
#define SM_HG1 91136     // 16896
#define SM_GL  108032    // 32*8*4 = 1024
#define SM_B2S 109056    // 808*4 = 3232
#define SMEM_TOTAL 112288

// fp16 weight scratch (converted+transposed once per launch; graph-deterministic)
__device__ __align__(16) __half g_W1h[E_DIM * H_DIM * D_DIM];  // [e][h][d]
__device__ __align__(16) __half g_W2h[E_DIM * C_DIM * H_DIM];  // [e][c][h]

__global__ void cvt_w1_kernel(const float* __restrict__ W1) {
    int idx = blockIdx.x * blockDim.x + threadIdx.x;
    if (idx >= E_DIM * H_DIM * D_DIM) return;
    int d = idx & (D_DIM - 1);
    int h = (idx >> 9) & (H_DIM - 1);
    int e = idx >> 17;
    g_W1h[idx] = __float2half_rn(W1[(e * D_DIM + d) * H_DIM + h]);
}

__global__ void cvt_w2_kernel(const float* __restrict__ W2) {
    int idx = blockIdx.x * blockDim.x + threadIdx.x;
    if (idx >= E_DIM * C_DIM * H_DIM) return;
    int h = idx & (H_DIM - 1);
    int t = idx >> 8;
    int c = t % C_DIM;
    int e = t / C_DIM;
    g_W2h[idx] = __float2half_rn(W2[(e * H_DIM + h) * C_DIM + c]);
}

// ---------------- PTX helpers ----------------
__device__ __forceinline__ void mma16816(float* c,
                                         unsigned a0, unsigned a1, unsigned a2, unsigned a3,
                                         unsigned b0, unsigned b1) {
    asm volatile(
        "mma.sync.aligned.m16n8k16.row.col.f32.f16.f16.f32 "
        "{%0,%1,%2,%3}, {%4,%5,%6,%7}, {%8,%9}, {%0,%1,%2,%3};\n"
        : "+f"(c[0]), "+f"(c[1]), "+f"(c[2]), "+f"(c[3])
        : "r"(a0), "r"(a1), "r"(a2), "r"(a3), "r"(b0), "r"(b1));
}
__device__ __forceinline__ void ldsm_x4(unsigned& r0, unsigned& r1, unsigned& r2,
                                        unsigned& r3, unsigned addr) {
    asm volatile("ldmatrix.sync.aligned.m8n8.x4.shared.b16 {%0,%1,%2,%3}, [%4];\n"
                 : "=r"(r0), "=r"(r1), "=r"(r2), "=r"(r3) : "r"(addr));
}
__device__ __forceinline__ void ldsm_x2(unsigned& r0, unsigned& r1, unsigned addr) {
    asm volatile("ldmatrix.sync.aligned.m8n8.x2.shared.b16 {%0,%1}, [%2];\n"
                 : "=r"(r0), "=r"(r1) : "r"(addr));
}
__device__ __forceinline__ unsigned su(const void* p) {
    return (unsigned)__cvta_generic_to_shared(p);
}
__device__ __forceinline__ void cpa16(unsigned dst, const void* src) {
    asm volatile("cp.async.cg.shared.global [%0], [%1], 16;\n" :: "r"(dst), "l"(src));
}
// zero-fill form: copies src_size bytes (0 or 16), zero-fills the rest
__device__ __forceinline__ void cpa16z(unsigned dst, const void* src, unsigned sz) {
    asm volatile("cp.async.cg.shared.global [%0], [%1], 16, %2;\n"
                 :: "r"(dst), "l"(src), "r"(sz));
}
__device__ __forceinline__ void cpa_commit() {
    asm volatile("cp.async.commit_group;\n" ::: "memory");
}
__device__ __forceinline__ void cpa_wait1() {
    asm volatile("cp.async.wait_group 1;\n" ::: "memory");
}
__device__ __forceinline__ void cpa_wait0() {
    asm volatile("cp.async.wait_group 0;\n" ::: "memory");
}

__global__ void __launch_bounds__(THREADS, 2)
moe_fused_kernel(const float* __restrict__ x,
                 const float* __restrict__ b1,
                 const float* __restrict__ b2,
                 const float* __restrict__ Wg,
                 const float* __restrict__ bg,
                 float* __restrict__ out) {
    extern __shared__ char smem[];
    __half* xhi = (__half*)(smem + SM_XHI);
    float*  gl  = (float*)(smem + SM_GL);
    float*  b2s = (float*)(smem + SM_B2S);

    const int tid  = threadIdx.x;
    const int w    = tid >> 5;      // warp id 0..7
    const int lane = tid & 31;
    const int gid  = lane >> 2;
    const int tg   = lane & 3;
    const int m0   = blockIdx.x * M_TILE;

    const unsigned xhi_u = su(xhi);
    const unsigned hg0_u = su(smem + SM_HG0);
    const unsigned hg1_u = su(smem + SM_HG1);
    const unsigned mybuf = su(smem + SM_WB) + w * (2 * BUF_SZ);   // warp-private ring

    // GEMM2 row split across warps: {16,16,16,16,16,8,8,8} rows -> 104 (C padded)
    const int n2base = (w < 5) ? w * 16 : 80 + (w - 5) * 8;
    const int nt2w   = (w < 5) ? 2 : 1;

    // ---- warp-private staging macros ----
    // W1 chunk: 32 rows (warp's n-slice) x 32 k halfs (64B = 4x16B per row)
    #define STAGE_W1(E, KCH, BUF) do {                                            \
        unsigned _d = mybuf + (BUF) * BUF_SZ;                                     \
        const __half* _s = g_W1h + ((size_t)(E) * H_DIM + w * 32) * D_DIM + (KCH) * KC; \
        _Pragma("unroll")                                                         \
        for (int _it = 0; _it < 4; _it++) {                                       \
            int _j = lane + _it * 32;                                             \
            int _r = _j >> 2, _ss = _j & 3;                                       \
            cpa16(_d + _r * B1PITCH + _ss * 16, _s + (size_t)_r * D_DIM + _ss * 8); \
        }                                                                         \
        cpa_commit();                                                             \
    } while (0)

    // W2 quarter: warp's row-slice x 64 k halfs (128B = 8x16B per row)
    #define STAGE_W2(E, P, BUF) do {                                              \
        unsigned _d = mybuf + (BUF) * BUF_SZ;                                     \
        const __half* _s = g_W2h + (size_t)(E) * C_DIM * H_DIM + (P) * 64;        \
        int _nops = nt2w * 8 * 8;                                                 \
        for (int _j = lane; _j < _nops; _j += 32) {                               \
            int _r = _j >> 3, _ss = _j & 7;                                       \
            int _c = n2base + _r;                                                 \
            int _ok = (_c < C_DIM);                                               \
            cpa16z(_d + _r * B2PITCH + _ss * 16,                                  \
                   _s + (size_t)(_ok ? _c : 0) * H_DIM + _ss * 8, _ok ? 16u : 0u); \
        }                                                                         \
        cpa_commit();                                                             \
    } while (0)

    // ---- prefetch expert-0 chunks 0/1 into the private ring immediately ----
    STAGE_W1(0, 0, 0);
    STAGE_W1(0, 1, 1);

    // ---- load x tile -> fp16 smem (overlaps cp.async) ----
    {
        const float4* xg = (const float4*)(x + (size_t)m0 * D_DIM);
        #pragma unroll 4
        for (int it = 0; it < 16; it++) {          // 32 rows * 128 float4
            int i  = tid + it * THREADS;
            int r  = i >> 7, c4 = i & 127;
            float4 v = xg[r * 128 + c4];
            __half2 h01 = __floats2half2_rn(v.x, v.y);
            __half2 h23 = __floats2half2_rn(v.z, v.w);
            *(uint2*)&xhi[r * XP + c4 * 4] = make_uint2(*(unsigned*)&h01, *(unsigned*)&h23);
        }
    }
    for (int i = tid; i < E_DIM * C_DIM; i += THREADS) b2s[i] = b2[i];
    __syncthreads();

    // ---- gate logits in full fp32 straight from gmem (L1-hot) ----
    {
        int row = tid >> 3;            // 0..31
        int e0  = tid & 7;             // 1 expert per thread
        const float* xr = x + (size_t)(m0 + row) * D_DIM;
        float s = 0.f;
        for (int d = 0; d < D_DIM; d += 4) {
            float4 xv = *(const float4*)&xr[d];
            s += xv.x * Wg[(d + 0) * E_DIM + e0] + xv.y * Wg[(d + 1) * E_DIM + e0]
               + xv.z * Wg[(d + 2) * E_DIM + e0] + xv.w * Wg[(d + 3) * E_DIM + e0];
        }
        gl[row * E_DIM + e0] = s + bg[e0];
    }
    __syncthreads();
    if (tid < M_TILE) {
        float l[8], m = -1e30f;
        #pragma unroll
        for (int e = 0; e < 8; e++) { l[e] = gl[tid * 8 + e]; m = fmaxf(m, l[e]); }
        float s = 0.f;
        #pragma unroll
        for (int e = 0; e < 8; e++) { l[e] = __expf(l[e] - m); s += l[e]; }
        float inv = 1.f / s;
        #pragma unroll
        for (int e = 0; e < 8; e++) gl[tid * 8 + e] = l[e] * inv;
    }
    __syncthreads();

    // ---- per-lane LDSM fragment offsets ----
    const unsigned aoffm = ((lane & 15) * XP + (lane >> 4) * 8) * 2;          // + mt*16*XP*2
    const unsigned aoffh = ((lane & 15) * HGP + (lane >> 4) * 8) * 2;
    const unsigned boff1 = ((lane & 7) + ((lane >> 3) & 1) * 8) * B1PITCH + (lane >> 4) * 16;
    const unsigned boff2 = ((lane & 7) + ((lane >> 3) & 1) * 8) * B2PITCH + (lane >> 4) * 16;
    const unsigned boff2s = (lane & 7) * B2PITCH + ((lane >> 3) & 1) * 16;

    float acc2[2][2][4];
    #pragma unroll
    for (int i = 0; i < 2; i++)
        #pragma unroll
        for (int j = 0; j < 2; j++)
            #pragma unroll
            for (int k = 0; k < 4; k++) acc2[i][j][k] = 0.f;

    for (int e = 0; e < E_DIM; e++) {
        // hg double-buffer: expert e uses buffer e&1; the publish barrier below
        // transitively protects reuse two experts later.
        const unsigned hg_w = (e & 1) ? hg1_u : hg0_u;
        __half* hgp = (__half*)(smem + ((e & 1) ? SM_HG1 : SM_HG0));

        float acc1[2][4][4];               // [mt][nt][4]
        #pragma unroll
        for (int i = 0; i < 2; i++)
            #pragma unroll
            for (int j = 0; j < 4; j++)
                #pragma unroll
                for (int k = 0; k < 4; k++) acc1[i][j][k] = 0.f;

        // ---- GEMM1: warp-async, 16 private K32 chunks, NO block barriers ----
        for (int kc = 0; kc < NCH; kc++) {
            cpa_wait1();
            __syncwarp();                  // my staged chunk visible warp-wide
            const unsigned bb = mybuf + (kc & 1) * BUF_SZ;
            #pragma unroll
            for (int ks = 0; ks < 2; ks++) {          // 2 k16 steps
                unsigned b0[4], b1f[4];
                ldsm_x4(b0[0], b0[1], b0[2], b0[3],  bb + boff1 + ks * 32);
                ldsm_x4(b1f[0], b1f[1], b1f[2], b1f[3],
                        bb + 16 * B1PITCH + boff1 + ks * 32);
                #pragma unroll
                for (int mt = 0; mt < 2; mt++) {
                    unsigned a0, a1, a2, a3;
                    ldsm_x4(a0, a1, a2, a3,
                            xhi_u + mt * (16 * XP * 2) + aoffm + (kc * KC + ks * 16) * 2);
                    mma16816(acc1[mt][0], a0, a1, a2, a3, b0[0],  b0[2]);
                    mma16816(acc1[mt][1], a0, a1, a2, a3, b0[1],  b0[3]);
                    mma16816(acc1[mt][2], a0, a1, a2, a3, b1f[0], b1f[2]);
                    mma16816(acc1[mt][3], a0, a1, a2, a3, b1f[1], b1f[3]);
                }
            }
            __syncwarp();                  // all lanes done reading buf
            if (kc < NCH - 2) { STAGE_W1(e, kc + 2, kc & 1); }
            else              { STAGE_W2(e, kc - (NCH - 2), kc & 1); }
        }

        // ---- epilogue: +b1, relu, *gate -> warp-private hg columns ----
        #pragma unroll
        for (int mt = 0; mt < 2; mt++) {
            const int r0 = mt * 16 + gid;
            float ge0 = gl[r0 * 8 + e];
            float ge1 = gl[(r0 + 8) * 8 + e];
            #pragma unroll
            for (int nt = 0; nt < 4; nt++) {
                int col = w * 32 + nt * 8 + tg * 2;
                float2 bb1 = *(const float2*)&b1[e * H_DIM + col];
                float v0 = fmaxf(acc1[mt][nt][0] + bb1.x, 0.f) * ge0;
                float v1 = fmaxf(acc1[mt][nt][1] + bb1.y, 0.f) * ge0;
                float v2 = fmaxf(acc1[mt][nt][2] + bb1.x, 0.f) * ge1;
                float v3 = fmaxf(acc1[mt][nt][3] + bb1.y, 0.f) * ge1;
                *(__half2*)&hgp[r0 * HGP + col]       = __floats2half2_rn(v0, v1);
                *(__half2*)&hgp[(r0 + 8) * HGP + col] = __floats2half2_rn(v2, v3);
            }
        }
        __syncthreads();                   // hg[e&1] published (sole barrier/expert)

        // ---- GEMM2: K=256 over 4 private W2 quarters (K64 each) ----
        for (int q = 0; q < 4; q++) {
            // RACE FIX (round 11): for the LAST expert, q=2 stages nothing, so at
            // q=3 only W2q3 is pending and wait_group 1 would NOT retire it.
            // Drain fully there instead.
            if (q == 3 && e == E_DIM - 1) cpa_wait0(); else cpa_wait1();
            __syncwarp();                  // quarter q staged
            const unsigned bb = mybuf + (q & 1) * BUF_SZ;
            #pragma unroll
            for (int ks = 0; ks < 4; ks++) {
                const unsigned kl = ks * 32;       // byte offset within quarter
                unsigned c0, c1, c2, c3;
                if (nt2w == 2) ldsm_x4(c0, c1, c2, c3, bb + boff2 + kl);
                else           ldsm_x2(c0, c1, bb + boff2s + kl);
                #pragma unroll
                for (int mt = 0; mt < 2; mt++) {
                    unsigned a0, a1, a2, a3;
                    ldsm_x4(a0, a1, a2, a3,
                            hg_w + mt * (16 * HGP * 2) + aoffh + (q * 64 + ks * 16) * 2);
                    if (nt2w == 2) {
                        mma16816(acc2[mt][0], a0, a1, a2, a3, c0, c2);
                        mma16816(acc2[mt][1], a0, a1, a2, a3, c1, c3);
                    } else {
                        mma16816(acc2[mt][0], a0, a1, a2, a3, c0, c1);
                    }
                }
            }
            __syncwarp();                  // quarter buf consumed
            if (q < 2)               { STAGE_W2(e, q + 2, q & 1); }
            else if (e + 1 < E_DIM)  { STAGE_W1(e + 1, q - 2, q & 1); }
        }
        // no end-of-expert barrier: warps flow directly into next GEMM1
    }

    // ---- final store: out = acc2 + sum_e g[e]*b2[e][c] ----
    #pragma unroll
    for (int mt = 0; mt < 2; mt++) {
        const int r0 = mt * 16 + gid;
        const float* gr0 = &gl[r0 * 8];
        const float* gr1 = &gl[(r0 + 8) * 8];
        #pragma unroll
        for (int nt = 0; nt < 2; nt++) {
            if (nt < nt2w) {
                int col = n2base + nt * 8 + tg * 2;
                #pragma unroll
                for (int cc = 0; cc < 2; cc++) {
                    int c = col + cc;
                    if (c < C_DIM) {
                        float bias0 = 0.f, bias1 = 0.f;
                        #pragma unroll
                        for (int ee = 0; ee < 8; ee++) {
                            float bv = b2s[ee * C_DIM + c];
                            bias0 += gr0[ee] * bv;
                            bias1 += gr1[ee] * bv;
                        }
                        out[(size_t)(m0 + r0) * C_DIM + c]     = acc2[mt][nt][cc] + bias0;
                        out[(size_t)(m0 + r0 + 8) * C_DIM + c] = acc2[mt][nt][2 + cc] + bias1;
                    }
                }
            }
        }
    }
}

extern "C" void kernel_launch(void* const* d_in, const int* in_sizes, int n_in,
                              void* d_out, int out_size) {
    (void)in_sizes; (void)n_in; (void)out_size;
    const float* x  = (const float*)d_in[0];
    const float* W1 = (const float*)d_in[1];
    const float* b1 = (const float*)d_in[2];
    const float* W2 = (const float*)d_in[3];
    const float* b2 = (const float*)d_in[4];
    const float* Wg = (const float*)d_in[5];
    const float* bg = (const float*)d_in[6];
    float* out = (float*)d_out;

    cvt_w1_kernel<<<(E_DIM * H_DIM * D_DIM + 255) / 256, 256>>>(W1);
    cvt_w2_kernel<<<(E_DIM * C_DIM * H_DIM + 255) / 256, 256>>>(W2);

    cudaFuncSetAttribute(moe_fused_kernel,
                         cudaFuncAttributeMaxDynamicSharedMemorySize, SMEM_TOTAL);
    moe_fused_kernel<<<B_ROWS / M_TILE, THREADS, SMEM_TOTAL>>>(x, b1, b2, Wg, bg, out);
}

// round 14
// speedup vs baseline: 1.0013x; 1.0013x over previous
#include <cuda_runtime.h>
#include <cuda_fp16.h>
#include <cstdint>

// Problem constants
#define B_ROWS 65536
#define D_DIM  512
#define C_DIM  101
#define E_DIM  8
#define H_DIM  256

#define THREADS 256
#define M_TILE 32
#define KC     32        // GEMM1 K-chunk (per-warp private staging)
#define NCH    16        // 512/32 chunks
#define XP     520       // fp16 pitch xhi (1040B; %128B=16 -> LDSM conflict-free)
#define HGP    264       // fp16 pitch hidden tile (528B; %128=16)
#define B1PITCH 80       // bytes/row, W1 ring (32 halfs + pad)
#define B2PITCH 144      // bytes/row, W2 ring (64 halfs + pad; %128=16)
#define BUF_SZ 2560      // one ring buffer: 32 rows x 80B (W2: 16 x 144 = 2304 fits)

// Shared memory layout (bytes) — 112288 total -> 2 CTAs/SM
#define SM_XHI 0         // 32*520*2 = 33280
#define SM_WB  33280     // 8 warps x 2 bufs x 2560 = 40960
#define SM_HG0 74240     // 32*264*2 = 16896
#define SM_HG1 91136     // 16896
#define SM_GL  108032    // 32*8*4 = 1024
#define SM_B2S 109056    // 808*4 = 3232
#define SMEM_TOTAL 112288

// fp16 weight scratch (converted+transposed once per launch; graph-deterministic)
__device__ __align__(16) __half g_W1h[E_DIM * H_DIM * D_DIM];  // [e][h][d]
__device__ __align__(16) __half g_W2h[E_DIM * C_DIM * H_DIM];  // [e][c][h]

__global__ void cvt_w1_kernel(const float* __restrict__ W1) {
    int idx = blockIdx.x * blockDim.x + threadIdx.x;
    if (idx >= E_DIM * H_DIM * D_DIM) return;
    int d = idx & (D_DIM - 1);
    int h = (idx >> 9) & (H_DIM - 1);
    int e = idx >> 17;
    g_W1h[idx] = __float2half_rn(W1[(e * D_DIM + d) * H_DIM + h]);
}

__global__ void cvt_w2_kernel(const float* __restrict__ W2) {
    int idx = blockIdx.x * blockDim.x + threadIdx.x;
    if (idx >= E_DIM * C_DIM * H_DIM) return;
    int h = idx & (H_DIM - 1);
    int t = idx >> 8;
    int c = t % C_DIM;
    int e = t / C_DIM;
    g_W2h[idx] = __float2half_rn(W2[(e * H_DIM + h) * C_DIM + c]);
}

// ---------------- PTX helpers ----------------
__device__ __forceinline__ void mma16816(float* c,
                                         unsigned a0, unsigned a1, unsigned a2, unsigned a3,
                                         unsigned b0, unsigned b1) {
    asm volatile(
        "mma.sync.aligned.m16n8k16.row.col.f32.f16.f16.f32 "
        "{%0,%1,%2,%3}, {%4,%5,%6,%7}, {%8,%9}, {%0,%1,%2,%3};\n"
        : "+f"(c[0]), "+f"(c[1]), "+f"(c[2]), "+f"(c[3])
        : "r"(a0), "r"(a1), "r"(a2), "r"(a3), "r"(b0), "r"(b1));
}
__device__ __forceinline__ void ldsm_x4(unsigned& r0, unsigned& r1, unsigned& r2,
                                        unsigned& r3, unsigned addr) {
    asm volatile("ldmatrix.sync.aligned.m8n8.x4.shared.b16 {%0,%1,%2,%3}, [%4];\n"
                 : "=r"(r0), "=r"(r1), "=r"(r2), "=r"(r3) : "r"(addr));
}
__device__ __forceinline__ void ldsm_x2(unsigned& r0, unsigned& r1, unsigned addr) {
    asm volatile("ldmatrix.sync.aligned.m8n8.x2.shared.b16 {%0,%1}, [%2];\n"
                 : "=r"(r0), "=r"(r1) : "r"(addr));
}
__device__ __forceinline__ unsigned su(const void* p) {
    return (unsigned)__cvta_generic_to_shared(p);
}
__device__ __forceinline__ void cpa16(unsigned dst, const void* src) {
    asm volatile("cp.async.cg.shared.global [%0], [%1], 16;\n" :: "r"(dst), "l"(src));
}
// zero-fill form: copies src_size bytes (0 or 16), zero-fills the rest
__device__ __forceinline__ void cpa16z(unsigned dst, const void* src, unsigned sz) {
    asm volatile("cp.async.cg.shared.global [%0], [%1], 16, %2;\n"
                 :: "r"(dst), "l"(src), "r"(sz));
}
__device__ __forceinline__ void cpa_commit() {
    asm volatile("cp.async.commit_group;\n" ::: "memory");
}
__device__ __forceinline__ void cpa_wait1() {
    asm volatile("cp.async.wait_group 1;\n" ::: "memory");
}
__device__ __forceinline__ void cpa_wait0() {
    asm volatile("cp.async.wait_group 0;\n" ::: "memory");
}

__global__ void __launch_bounds__(THREADS, 2)
moe_fused_kernel(const float* __restrict__ x,
                 const float* __restrict__ b1,
                 const float* __restrict__ b2,
                 const float* __restrict__ Wg,
                 const float* __restrict__ bg,
                 float* __restrict__ out) {
    extern __shared__ char smem[];
    __half* xhi = (__half*)(smem + SM_XHI);
    float*  gl  = (float*)(smem + SM_GL);
    float*  b2s = (float*)(smem + SM_B2S);

    const int tid  = threadIdx.x;
    const int w    = tid >> 5;      // warp id 0..7
    const int lane = tid & 31;
    const int gid  = lane >> 2;
    const int tg   = lane & 3;
    const int m0   = blockIdx.x * M_TILE;

    const unsigned xhi_u = su(xhi);
    const unsigned hg0_u = su(smem + SM_HG0);
    const unsigned hg1_u = su(smem + SM_HG1);
    const unsigned mybuf = su(smem + SM_WB) + w * (2 * BUF_SZ);   // warp-private ring

    // GEMM2 row split across warps: {16,16,16,16,16,8,8,8} rows -> 104 (C padded)
    const int n2base = (w < 5) ? w * 16 : 80 + (w - 5) * 8;
    const int nt2w   = (w < 5) ? 2 : 1;

    // ---- warp-private staging macros ----
    // W1 chunk: 32 rows (warp's n-slice) x 32 k halfs (64B = 4x16B per row)
    #define STAGE_W1(E, KCH, BUF) do {                                            \
        unsigned _d = mybuf + (BUF) * BUF_SZ;                                     \
        const __half* _s = g_W1h + ((size_t)(E) * H_DIM + w * 32) * D_DIM + (KCH) * KC; \
        _Pragma("unroll")                                                         \
        for (int _it = 0; _it < 4; _it++) {                                       \
            int _j = lane + _it * 32;                                             \
            int _r = _j >> 2, _ss = _j & 3;                                       \
            cpa16(_d + _r * B1PITCH + _ss * 16, _s + (size_t)_r * D_DIM + _ss * 8); \
        }                                                                         \
        cpa_commit();                                                             \
    } while (0)

    // W2 quarter: warp's row-slice x 64 k halfs (128B = 8x16B per row)
    #define STAGE_W2(E, P, BUF) do {                                              \
        unsigned _d = mybuf + (BUF) * BUF_SZ;                                     \
        const __half* _s = g_W2h + (size_t)(E) * C_DIM * H_DIM + (P) * 64;        \
        int _nops = nt2w * 8 * 8;                                                 \
        for (int _j = lane; _j < _nops; _j += 32) {                               \
            int _r = _j >> 3, _ss = _j & 7;                                       \
            int _c = n2base + _r;                                                 \
            int _ok = (_c < C_DIM);                                               \
            cpa16z(_d + _r * B2PITCH + _ss * 16,                                  \
                   _s + (size_t)(_ok ? _c : 0) * H_DIM + _ss * 8, _ok ? 16u : 0u); \
        }                                                                         \
        cpa_commit();                                                             \
    } while (0)

    // ---- prefetch expert-0 chunks 0/1 into the private ring immediately ----
    STAGE_W1(0, 0, 0);
    STAGE_W1(0, 1, 1);

    // ---- load x tile -> fp16 smem (overlaps cp.async) ----
    {
        const float4* xg = (const float4*)(x + (size_t)m0 * D_DIM);
        #pragma unroll 4
        for (int it = 0; it < 16; it++) {          // 32 rows * 128 float4
            int i  = tid + it * THREADS;
            int r  = i >> 7, c4 = i & 127;
            float4 v = xg[r * 128 + c4];
            __half2 h01 = __floats2half2_rn(v.x, v.y);
            __half2 h23 = __floats2half2_rn(v.z, v.w);
            *(uint2*)&xhi[r * XP + c4 * 4] = make_uint2(*(unsigned*)&h01, *(unsigned*)&h23);
        }
    }
    for (int i = tid; i < E_DIM * C_DIM; i += THREADS) b2s[i] = b2[i];
    __syncthreads();

    // ---- gate logits in full fp32 straight from gmem (L1-hot) ----
    {
        int row = tid >> 3;            // 0..31
        int e0  = tid & 7;             // 1 expert per thread
        const float* xr = x + (size_t)(m0 + row) * D_DIM;
        float s = 0.f;
        for (int d = 0; d < D_DIM; d += 4) {
            float4 xv = *(const float4*)&xr[d];
            s += xv.x * Wg[(d + 0) * E_DIM + e0] + xv.y * Wg[(d + 1) * E_DIM + e0]
               + xv.z * Wg[(d + 2) * E_DIM + e0] + xv.w * Wg[(d + 3) * E_DIM + e0];
        }
        gl[row * E_DIM + e0] = s + bg[e0];
    }
    __syncthreads();
    if (tid < M_TILE) {
        float l[8], m = -1e30f;
        #pragma unroll
        for (int e = 0; e < 8; e++) { l[e] = gl[tid * 8 + e]; m = fmaxf(m, l[e]); }
        float s = 0.f;
        #pragma unroll
        for (int e = 0; e < 8; e++) { l[e] = __expf(l[e] - m); s += l[e]; }
        float inv = 1.f / s;
        #pragma unroll
        for (int e = 0; e < 8; e++) gl[tid * 8 + e] = l[e] * inv;
    }
    __syncthreads();

    // ---- per-lane LDSM fragment offsets ----
    const unsigned aoffm = ((lane & 15) * XP + (lane >> 4) * 8) * 2;          // + mt*16*XP*2
    const unsigned aoffh = ((lane & 15) * HGP + (lane >> 4) * 8) * 2;
    const unsigned boff1 = ((lane & 7) + ((lane >> 3) & 1) * 8) * B1PITCH + (lane >> 4) * 16;
    const unsigned boff2 = ((lane & 7) + ((lane >> 3) & 1) * 8) * B2PITCH + (lane >> 4) * 16;
    const unsigned boff2s = (lane & 7) * B2PITCH + ((lane >> 3) & 1) * 16;

    float acc2[2][2][4];
    #pragma unroll
    for (int i = 0; i < 2; i++)
        #pragma unroll
        for (int j = 0; j < 2; j++)
            #pragma unroll
            for (int k = 0; k < 4; k++) acc2[i][j][k] = 0.f;

    for (int e = 0; e < E_DIM; e++) {
        // hg double-buffer: expert e uses buffer e&1; the publish barrier below
        // transitively protects reuse two experts later.
        const unsigned hg_w = (e & 1) ? hg1_u : hg0_u;
        __half* hgp = (__half*)(smem + ((e & 1) ? SM_HG1 : SM_HG0));

        float acc1[2][4][4];               // [mt][nt][4]
        #pragma unroll
        for (int i = 0; i < 2; i++)
            #pragma unroll
            for (int j = 0; j < 4; j++)
                #pragma unroll
                for (int k = 0; k < 4; k++) acc1[i][j][k] = 0.f;

        // ---- GEMM1: warp-async, 16 private K32 chunks, NO block barriers ----
        for (int kc = 0; kc < NCH; kc++) {
            cpa_wait1();
            __syncwarp();                  // my staged chunk visible warp-wide
            const unsigned bb = mybuf + (kc & 1) * BUF_SZ;
            #pragma unroll
            for (int ks = 0; ks < 2; ks++) {          // 2 k16 steps
                unsigned b0[4], b1f[4];
                ldsm_x4(b0[0], b0[1], b0[2], b0[3],  bb + boff1 + ks * 32);
                ldsm_x4(b1f[0], b1f[1], b1f[2], b1f[3],
                        bb + 16 * B1PITCH + boff1 + ks * 32);
                #pragma unroll
                for (int mt = 0; mt < 2; mt++) {
                    unsigned a0, a1, a2, a3;
                    ldsm_x4(a0, a1, a2, a3,
                            xhi_u + mt * (16 * XP * 2) + aoffm + (kc * KC + ks * 16) * 2);
                    mma16816(acc1[mt][0], a0, a1, a2, a3, b0[0],  b0[2]);
                    mma16816(acc1[mt][1], a0, a1, a2, a3, b0[1],  b0[3]);
                    mma16816(acc1[mt][2], a0, a1, a2, a3, b1f[0], b1f[2]);
                    mma16816(acc1[mt][3], a0, a1, a2, a3, b1f[1], b1f[3]);
                }
            }
            __syncwarp();                  // all lanes done reading buf
            if (kc < NCH - 2) { STAGE_W1(e, kc + 2, kc & 1); }
            else              { STAGE_W2(e, kc - (NCH - 2), kc & 1); }
        }

        // ---- epilogue: +b1, relu, *gate -> warp-private hg columns ----
        #pragma unroll
        for (int mt = 0; mt < 2; mt++) {
            const int r0 = mt * 16 + gid;
            float ge0 = gl[r0 * 8 + e];
            float ge1 = gl[(r0 + 8) * 8 + e];
            #pragma unroll
            for (int nt = 0; nt < 4; nt++) {
                int col = w * 32 + nt * 8 + tg * 2;
                float2 bb1 = *(const float2*)&b1[e * H_DIM + col];
                float v0 = fmaxf(acc1[mt][nt][0] + bb1.x, 0.f) * ge0;
                float v1 = fmaxf(acc1[mt][nt][1] + bb1.y, 0.f) * ge0;
                float v2 = fmaxf(acc1[mt][nt][2] + bb1.x, 0.f) * ge1;
                float v3 = fmaxf(acc1[mt][nt][3] + bb1.y, 0.f) * ge1;
                *(__half2*)&hgp[r0 * HGP + col]       = __floats2half2_rn(v0, v1);
                *(__half2*)&hgp[(r0 + 8) * HGP + col] = __floats2half2_rn(v2, v3);
            }
        }
        __syncthreads();                   // hg[e&1] published (sole barrier/expert)

        // ---- GEMM2: K=256 over 4 private W2 quarters (K64 each) ----
        for (int q = 0; q < 4; q++) {
            // RACE FIX (round 11): for the LAST expert, q=2 stages nothing, so at
            // q=3 only W2q3 is pending and wait_group 1 would NOT retire it.
            // Drain fully there instead.
            if (q == 3 && e == E_DIM - 1) cpa_wait0(); else cpa_wait1();
            __syncwarp();                  // quarter q staged
            const unsigned bb = mybuf + (q & 1) * BUF_SZ;
            #pragma unroll
            for (int ks = 0; ks < 4; ks++) {
                const unsigned kl = ks * 32;       // byte offset within quarter
                unsigned c0, c1, c2, c3;
                if (nt2w == 2) ldsm_x4(c0, c1, c2, c3, bb + boff2 + kl);
                else           ldsm_x2(c0, c1, bb + boff2s + kl);
                #pragma unroll
                for (int mt = 0; mt < 2; mt++) {
                    unsigned a0, a1, a2, a3;
                    ldsm_x4(a0, a1, a2, a3,
                            hg_w + mt * (16 * HGP * 2) + aoffh + (q * 64 + ks * 16) * 2);
                    if (nt2w == 2) {
                        mma16816(acc2[mt][0], a0, a1, a2, a3, c0, c2);
                        mma16816(acc2[mt][1], a0, a1, a2, a3, c1, c3);
                    } else {
                        mma16816(acc2[mt][0], a0, a1, a2, a3, c0, c1);
                    }
                }
            }
            __syncwarp();                  // quarter buf consumed
            if (q < 2)               { STAGE_W2(e, q + 2, q & 1); }
            else if (e + 1 < E_DIM)  { STAGE_W1(e + 1, q - 2, q & 1); }
        }
        // no end-of-expert barrier: warps flow directly into next GEMM1
    }

    // ---- final store: out = acc2 + sum_e g[e]*b2[e][c] ----
    #pragma unroll
    for (int mt = 0; mt < 2; mt++) {
        const int r0 = mt * 16 + gid;
        const float* gr0 = &gl[r0 * 8];
        const float* gr1 = &gl[(r0 + 8) * 8];
        #pragma unroll
        for (int nt = 0; nt < 2; nt++) {
            if (nt < nt2w) {
                int col = n2base + nt * 8 + tg * 2;
                #pragma unroll
                for (int cc = 0; cc < 2; cc++) {
                    int c = col + cc;
                    if (c < C_DIM) {
                        float bias0 = 0.f, bias1 = 0.f;
                        #pragma unroll
                        for (int ee = 0; ee < 8; ee++) {
                            float bv = b2s[ee * C_DIM + c];
                            bias0 += gr0[ee] * bv;
                            bias1 += gr1[ee] * bv;
                        }
                        out[(size_t)(m0 + r0) * C_DIM + c]     = acc2[mt][nt][cc] + bias0;
                        out[(size_t)(m0 + r0 + 8) * C_DIM + c] = acc2[mt][nt][2 + cc] + bias1;
                    }
                }
            }
        }
    }
}

extern "C" void kernel_launch(void* const* d_in, const int* in_sizes, int n_in,
                              void* d_out, int out_size) {
    (void)in_sizes; (void)n_in; (void)out_size;
    const float* x  = (const float*)d_in[0];
    const float* W1 = (const float*)d_in[1];
    const float* b1 = (const float*)d_in[2];
    const float* W2 = (const float*)d_in[3];
    const float* b2 = (const float*)d_in[4];
    const float* Wg = (const float*)d_in[5];
    const float* bg = (const float*)d_in[6];
    float* out = (float*)d_out;

    cvt_w1_kernel<<<(E_DIM * H_DIM * D_DIM + 255) / 256, 256>>>(W1);
    cvt_w2_kernel<<<(E_DIM * C_DIM * H_DIM + 255) / 256, 256>>>(W2);

    cudaFuncSetAttribute(moe_fused_kernel,
                         cudaFuncAttributeMaxDynamicSharedMemorySize, SMEM_TOTAL);
    moe_fused_kernel<<<B_ROWS / M_TILE, THREADS, SMEM_TOTAL>>>(x, b1, b2, Wg, bg, out);
}

// round 16
// speedup vs baseline: 1.1089x; 1.1075x over previous
#include <cuda_runtime.h>
#include <cuda_fp16.h>
#include <cstdint>

// Problem constants
#define B_ROWS 65536
#define D_DIM  512
#define C_DIM  101
#define E_DIM  8
#define H_DIM  256

#define THREADS 256
#define M_TILE 64
#define KC     64        // GEMM1 K-chunk (per-warp private staging)
#define NCH    8         // 512/64 chunks
#define XP     520       // fp16 pitch xhi (1040B; %128B=16 -> LDSM conflict-free)
#define HGP    264       // fp16 pitch hidden tile (528B; %128=16)
#define B1PITCH 144      // bytes/row, W1 ring (64 halfs + pad; %128=16)
#define B2PITCH 272      // bytes/row, W2 ring (128 halfs + pad; %128=16)
#define BUF_SZ 4608      // one ring buffer: 32 rows x 144B (W2: 16 x 272 = 4352 fits)

// Shared memory layout (bytes)
#define SM_XHI 0         // 66560
#define SM_WB  66560     // 8 warps x 2 bufs x 4608 = 73728
#define SM_HG0 140288    // 33792 (expert e, e even)
#define SM_HG1 174080    // 33792 (expert e, e odd)
#define SM_GL  207872    // 64*8*4 = 2048
#define SM_B2S 209920    // 808*4 = 3232
#define SMEM_TOTAL 213152

// fp16 weight scratch (converted+transposed once per launch; graph-deterministic)
__device__ __align__(16) __half g_W1h[E_DIM * H_DIM * D_DIM];  // [e][h][d]
__device__ __align__(16) __half g_W2h[E_DIM * C_DIM * H_DIM];  // [e][c][h]

// ---- coalesced tiled-transpose converters ----
// W1 [e][d][h] fp32 -> g_W1h [e][h][d] fp16.  grid (16,8,8), block (32,8)
__global__ void cvt_w1_kernel(const float* __restrict__ W1) {
    __shared__ float t[32][33];
    const int e  = blockIdx.z;
    const int d0 = blockIdx.x * 32;
    const int h0 = blockIdx.y * 32;
    const float* src = W1 + ((size_t)e * D_DIM + d0) * H_DIM + h0;
    #pragma unroll
    for (int i = 0; i < 32; i += 8)
        t[threadIdx.y + i][threadIdx.x] = src[(size_t)(threadIdx.y + i) * H_DIM + threadIdx.x];
    __syncthreads();
    __half* dst = g_W1h + ((size_t)e * H_DIM + h0) * D_DIM + d0;
    #pragma unroll
    for (int i = 0; i < 32; i += 8)
        dst[(size_t)(threadIdx.y + i) * D_DIM + threadIdx.x] =
            __float2half_rn(t[threadIdx.x][threadIdx.y + i]);
}

// W2 [e][h][c] fp32 -> g_W2h [e][c][h] fp16.  grid (8,4,8), block (32,8)
__global__ void cvt_w2_kernel(const float* __restrict__ W2) {
    __shared__ float t[32][33];
    const int e  = blockIdx.z;
    const int h0 = blockIdx.x * 32;
    const int c0 = blockIdx.y * 32;
    const float* src = W2 + ((size_t)e * H_DIM + h0) * C_DIM;
    #pragma unroll
    for (int i = 0; i < 32; i += 8) {
        int c = c0 + threadIdx.x;
        if (c < C_DIM)
            t[threadIdx.y + i][threadIdx.x] = src[(size_t)(threadIdx.y + i) * C_DIM + c];
    }
    __syncthreads();
    #pragma unroll
    for (int i = 0; i < 32; i += 8) {
        int c = c0 + threadIdx.y + i;
        if (c < C_DIM)
            g_W2h[((size_t)e * C_DIM + c) * H_DIM + h0 + threadIdx.x] =
                __float2half_rn(t[threadIdx.x][threadIdx.y + i]);
    }
}

// ---------------- PTX helpers ----------------
__device__ __forceinline__ void mma16816(float* c,
                                         unsigned a0, unsigned a1, unsigned a2, unsigned a3,
                                         unsigned b0, unsigned b1) {
    asm volatile(
        "mma.sync.aligned.m16n8k16.row.col.f32.f16.f16.f32 "
        "{%0,%1,%2,%3}, {%4,%5,%6,%7}, {%8,%9}, {%0,%1,%2,%3};\n"
        : "+f"(c[0]), "+f"(c[1]), "+f"(c[2]), "+f"(c[3])
        : "r"(a0), "r"(a1), "r"(a2), "r"(a3), "r"(b0), "r"(b1));
}
__device__ __forceinline__ void ldsm_x4(unsigned& r0, unsigned& r1, unsigned& r2,
                                        unsigned& r3, unsigned addr) {
    asm volatile("ldmatrix.sync.aligned.m8n8.x4.shared.b16 {%0,%1,%2,%3}, [%4];\n"
                 : "=r"(r0), "=r"(r1), "=r"(r2), "=r"(r3) : "r"(addr));
}
__device__ __forceinline__ void ldsm_x2(unsigned& r0, unsigned& r1, unsigned addr) {
    asm volatile("ldmatrix.sync.aligned.m8n8.x2.shared.b16 {%0,%1}, [%2];\n"
                 : "=r"(r0), "=r"(r1) : "r"(addr));
}
__device__ __forceinline__ unsigned su(const void* p) {
    return (unsigned)__cvta_generic_to_shared(p);
}
__device__ __forceinline__ void cpa16(unsigned dst, const void* src) {
    asm volatile("cp.async.cg.shared.global [%0], [%1], 16;\n" :: "r"(dst), "l"(src));
}
// zero-fill form: copies src_size bytes (0 or 16), zero-fills the rest
__device__ __forceinline__ void cpa16z(unsigned dst, const void* src, unsigned sz) {
    asm volatile("cp.async.cg.shared.global [%0], [%1], 16, %2;\n"
                 :: "r"(dst), "l"(src), "r"(sz));
}
__device__ __forceinline__ void cpa_commit() {
    asm volatile("cp.async.commit_group;\n" ::: "memory");
}
__device__ __forceinline__ void cpa_wait1() {
    asm volatile("cp.async.wait_group 1;\n" ::: "memory");
}
__device__ __forceinline__ void cpa_wait0() {
    asm volatile("cp.async.wait_group 0;\n" ::: "memory");
}

__global__ void __launch_bounds__(THREADS, 1)
moe_fused_kernel(const float* __restrict__ x,
                 const float* __restrict__ b1,
                 const float* __restrict__ b2,
                 const float* __restrict__ Wg,
                 const float* __restrict__ bg,
                 float* __restrict__ out) {
    extern __shared__ char smem[];
    __half* xhi = (__half*)(smem + SM_XHI);
    float*  gl  = (float*)(smem + SM_GL);
    float*  b2s = (float*)(smem + SM_B2S);

    const int tid  = threadIdx.x;
    const int w    = tid >> 5;      // warp id 0..7
    const int lane = tid & 31;
    const int gid  = lane >> 2;
    const int tg   = lane & 3;
    const int m0   = blockIdx.x * M_TILE;

    const unsigned xhi_u = su(xhi);
    const unsigned hg0_u = su(smem + SM_HG0);
    const unsigned hg1_u = su(smem + SM_HG1);
    const unsigned mybuf = su(smem + SM_WB) + w * (2 * BUF_SZ);   // warp-private ring

    // GEMM2 row split across warps: {16,16,16,16,16,8,8,8} rows -> 104 (C padded)
    const int n2base = (w < 5) ? w * 16 : 80 + (w - 5) * 8;
    const int nt2w   = (w < 5) ? 2 : 1;

    // ---- warp-private staging macros ----
    #define STAGE_W1(E, KCH, BUF) do {                                            \
        unsigned _d = mybuf + (BUF) * BUF_SZ;                                     \
        const __half* _s = g_W1h + ((size_t)(E) * H_DIM + w * 32) * D_DIM + (KCH) * KC; \
        _Pragma("unroll")                                                         \
        for (int _it = 0; _it < 8; _it++) {                                       \
            int _j = lane + _it * 32;                                             \
            int _r = _j >> 3, _ss = _j & 7;                                       \
            cpa16(_d + _r * B1PITCH + _ss * 16, _s + (size_t)_r * D_DIM + _ss * 8); \
        }                                                                         \
        cpa_commit();                                                             \
    } while (0)

    #define STAGE_W2(E, P, BUF) do {                                              \
        unsigned _d = mybuf + (BUF) * BUF_SZ;                                     \
        const __half* _s = g_W2h + (size_t)(E) * C_DIM * H_DIM + (P) * 128;       \
        int _nr = nt2w * 8;                                                       \
        for (int _j = lane; _j < _nr * 16; _j += 32) {                            \
            int _r = _j >> 4, _ss = _j & 15;                                      \
            int _c = n2base + _r;                                                 \
            int _ok = (_c < C_DIM);                                               \
            cpa16z(_d + _r * B2PITCH + _ss * 16,                                  \
                   _s + (size_t)(_ok ? _c : 0) * H_DIM + _ss * 8, _ok ? 16u : 0u); \
        }                                                                         \
        cpa_commit();                                                             \
    } while (0)

    // ---- prefetch expert-0 chunks 0/1 into the private ring immediately ----
    STAGE_W1(0, 0, 0);
    STAGE_W1(0, 1, 1);

    // ---- load x tile -> fp16 smem (overlaps cp.async) ----
    {
        const float4* xg = (const float4*)(x + (size_t)m0 * D_DIM);
        #pragma unroll 4
        for (int it = 0; it < 32; it++) {          // 64 rows * 128 float4
            int i  = tid + it * THREADS;
            int r  = i >> 7, c4 = i & 127;
            float4 v = xg[r * 128 + c4];
            __half2 h01 = __floats2half2_rn(v.x, v.y);
            __half2 h23 = __floats2half2_rn(v.z, v.w);
            *(uint2*)&xhi[r * XP + c4 * 4] = make_uint2(*(unsigned*)&h01, *(unsigned*)&h23);
        }
    }
    for (int i = tid; i < E_DIM * C_DIM; i += THREADS) b2s[i] = b2[i];
    __syncthreads();                               // x + b2s ready

    // ---- warp-specialized gate: warps 0-3 compute logits + softmax while
    //      warps 4-7 proceed straight into GEMM1 and keep the tensor pipe fed.
    //      Gates are published to all warps by the e==0 __syncthreads below.
    if (tid < 128) {
        int row = tid >> 1;            // 0..63
        int e4  = (tid & 1) * 4;       // experts e4..e4+3
        const float* xr  = x + (size_t)(m0 + row) * D_DIM;
        const float* wgp = Wg + e4;
        float s0 = 0.f, s1 = 0.f, s2 = 0.f, s3 = 0.f;
        for (int d = 0; d < D_DIM; d += 4) {
            float4 xv = *(const float4*)&xr[d];
            float4 w0 = *(const float4*)&wgp[(d + 0) * E_DIM];
            float4 w1 = *(const float4*)&wgp[(d + 1) * E_DIM];
            float4 w2 = *(const float4*)&wgp[(d + 2) * E_DIM];
            float4 w3 = *(const float4*)&wgp[(d + 3) * E_DIM];
            s0 += xv.x * w0.x + xv.y * w1.x + xv.z * w2.x + xv.w * w3.x;
            s1 += xv.x * w0.y + xv.y * w1.y + xv.z * w2.y + xv.w * w3.y;
            s2 += xv.x * w0.z + xv.y * w1.z + xv.z * w2.z + xv.w * w3.z;
            s3 += xv.x * w0.w + xv.y * w1.w + xv.z * w2.w + xv.w * w3.w;
        }
        gl[row * E_DIM + e4 + 0] = s0 + bg[e4 + 0];
        gl[row * E_DIM + e4 + 1] = s1 + bg[e4 + 1];
        gl[row * E_DIM + e4 + 2] = s2 + bg[e4 + 2];
        gl[row * E_DIM + e4 + 3] = s3 + bg[e4 + 3];
        asm volatile("bar.sync 1, 128;" ::: "memory");   // warps 0-3 only
        if (tid < M_TILE) {
            float l[8], m = -1e30f;
            #pragma unroll
            for (int e = 0; e < 8; e++) { l[e] = gl[tid * 8 + e]; m = fmaxf(m, l[e]); }
            float s = 0.f;
            #pragma unroll
            for (int e = 0; e < 8; e++) { l[e] = __expf(l[e] - m); s += l[e]; }
            float inv = 1.f / s;
            #pragma unroll
            for (int e = 0; e < 8; e++) gl[tid * 8 + e] = l[e] * inv;
        }
    }

    // ---- per-lane LDSM fragment offsets ----
    const unsigned aoffm = ((lane & 15) * XP + (lane >> 4) * 8) * 2;          // + mt*16*XP*2
    const unsigned aoffh = ((lane & 15) * HGP + (lane >> 4) * 8) * 2;
    const unsigned boff1 = ((lane & 7) + ((lane >> 3) & 1) * 8) * B1PITCH + (lane >> 4) * 16;
    const unsigned boff2 = ((lane & 7) + ((lane >> 3) & 1) * 8) * B2PITCH + (lane >> 4) * 16;
    const unsigned boff2s = (lane & 7) * B2PITCH + ((lane >> 3) & 1) * 16;

    float acc2[4][2][4];
    #pragma unroll
    for (int i = 0; i < 4; i++)
        #pragma unroll
        for (int j = 0; j < 2; j++)
            #pragma unroll
            for (int k = 0; k < 4; k++) acc2[i][j][k] = 0.f;

    for (int e = 0; e < E_DIM; e++) {
        // hg double-buffer: expert e uses buffer e&1; the publish barrier below
        // transitively protects reuse two experts later.
        const unsigned hg_w = (e & 1) ? hg1_u : hg0_u;
        __half* hgp = (__half*)(smem + ((e & 1) ? SM_HG1 : SM_HG0));

        float acc1[4][4][4];               // [mt][nt][4]
        #pragma unroll
        for (int i = 0; i < 4; i++)
            #pragma unroll
            for (int j = 0; j < 4; j++)
                #pragma unroll
                for (int k = 0; k < 4; k++) acc1[i][j][k] = 0.f;

        // ---- GEMM1: warp-async, 8 private K64 chunks, NO block barriers ----
        for (int kc = 0; kc < NCH; kc++) {
            cpa_wait1();
            __syncwarp();                  // my staged chunk visible warp-wide
            const unsigned bb = mybuf + (kc & 1) * BUF_SZ;
            #pragma unroll
            for (int ks = 0; ks < 4; ks++) {          // 4 k16 steps
                unsigned b0[4], b1f[4];
                ldsm_x4(b0[0], b0[1], b0[2], b0[3],  bb + boff1 + ks * 32);
                ldsm_x4(b1f[0], b1f[1], b1f[2], b1f[3],
                        bb + 16 * B1PITCH + boff1 + ks * 32);
                #pragma unroll
                for (int mt = 0; mt < 4; mt++) {
                    unsigned a0, a1, a2, a3;
                    ldsm_x4(a0, a1, a2, a3,
                            xhi_u + mt * (16 * XP * 2) + aoffm + (kc * KC + ks * 16) * 2);
                    mma16816(acc1[mt][0], a0, a1, a2, a3, b0[0],  b0[2]);
                    mma16816(acc1[mt][1], a0, a1, a2, a3, b0[1],  b0[3]);
                    mma16816(acc1[mt][2], a0, a1, a2, a3, b1f[0], b1f[2]);
                    mma16816(acc1[mt][3], a0, a1, a2, a3, b1f[1], b1f[3]);
                }
            }
            __syncwarp();                  // all lanes done reading buf
            if (kc < NCH - 2) { STAGE_W1(e, kc + 2, kc & 1); }
            else              { STAGE_W2(e, kc - (NCH - 2), kc & 1); }
        }

        if (e == 0) __syncthreads();       // gates (softmax) published to all warps

        // ---- epilogue: +b1, relu, *gate -> warp-private hg columns ----
        #pragma unroll
        for (int mt = 0; mt < 4; mt++) {
            const int r0 = mt * 16 + gid;
            float ge0 = gl[r0 * 8 + e];
            float ge1 = gl[(r0 + 8) * 8 + e];
            #pragma unroll
            for (int nt = 0; nt < 4; nt++) {
                int col = w * 32 + nt * 8 + tg * 2;
                float2 bb1 = *(const float2*)&b1[e * H_DIM + col];
                float v0 = fmaxf(acc1[mt][nt][0] + bb1.x, 0.f) * ge0;
                float v1 = fmaxf(acc1[mt][nt][1] + bb1.y, 0.f) * ge0;
                float v2 = fmaxf(acc1[mt][nt][2] + bb1.x, 0.f) * ge1;
                float v3 = fmaxf(acc1[mt][nt][3] + bb1.y, 0.f) * ge1;
                *(__half2*)&hgp[r0 * HGP + col]       = __floats2half2_rn(v0, v1);
                *(__half2*)&hgp[(r0 + 8) * HGP + col] = __floats2half2_rn(v2, v3);
            }
        }
        __syncthreads();                   // hg[e&1] published (sole barrier/expert)

        // ---- GEMM2: K=256 over 2 private W2 halves ----
        cpa_wait0();
        __syncwarp();
        #pragma unroll
        for (int ks = 0; ks < 16; ks++) {
            const int p = ks >> 3;
            const unsigned bb = mybuf + p * BUF_SZ;
            const unsigned kl = (ks & 7) * 32;     // byte offset within half
            unsigned c0, c1, c2, c3;
            if (nt2w == 2) ldsm_x4(c0, c1, c2, c3, bb + boff2 + kl);
            else           ldsm_x2(c0, c1, bb + boff2s + kl);
            #pragma unroll
            for (int mt = 0; mt < 4; mt++) {
                unsigned a0, a1, a2, a3;
                ldsm_x4(a0, a1, a2, a3,
                        hg_w + mt * (16 * HGP * 2) + aoffh + ks * 32);
                if (nt2w == 2) {
                    mma16816(acc2[mt][0], a0, a1, a2, a3, c0, c2);
                    mma16816(acc2[mt][1], a0, a1, a2, a3, c1, c3);
                } else {
                    mma16816(acc2[mt][0], a0, a1, a2, a3, c0, c1);
                }
            }
            if (ks == 7 && e + 1 < E_DIM) {        // buf0 consumed: prefetch next W1
                __syncwarp();
                STAGE_W1(e + 1, 0, 0);
            }
        }
        __syncwarp();
        if (e + 1 < E_DIM) { STAGE_W1(e + 1, 1, 1); }
        // no end-of-expert barrier: warps flow directly into next GEMM1
    }

    // ---- final store: out = acc2 + sum_e g[e]*b2[e][c] ----
    #pragma unroll
    for (int mt = 0; mt < 4; mt++) {
        const int r0 = mt * 16 + gid;
        const float* gr0 = &gl[r0 * 8];
        const float* gr1 = &gl[(r0 + 8) * 8];
        #pragma unroll
        for (int nt = 0; nt < 2; nt++) {
            if (nt < nt2w) {
                int col = n2base + nt * 8 + tg * 2;
                #pragma unroll
                for (int cc = 0; cc < 2; cc++) {
                    int c = col + cc;
                    if (c < C_DIM) {
                        float bias0 = 0.f, bias1 = 0.f;
                        #pragma unroll
                        for (int ee = 0; ee < 8; ee++) {
                            float bv = b2s[ee * C_DIM + c];
                            bias0 += gr0[ee] * bv;
                            bias1 += gr1[ee] * bv;
                        }
                        out[(size_t)(m0 + r0) * C_DIM + c]     = acc2[mt][nt][cc] + bias0;
                        out[(size_t)(m0 + r0 + 8) * C_DIM + c] = acc2[mt][nt][2 + cc] + bias1;
                    }
                }
            }
        }
    }
}

extern "C" void kernel_launch(void* const* d_in, const int* in_sizes, int n_in,
                              void* d_out, int out_size) {
    (void)in_sizes; (void)n_in; (void)out_size;
    const float* x  = (const float*)d_in[0];
    const float* W1 = (const float*)d_in[1];
    const float* b1 = (const float*)d_in[2];
    const float* W2 = (const float*)d_in[3];
    const float* b2 = (const float*)d_in[4];
    const float* Wg = (const float*)d_in[5];
    const float* bg = (const float*)d_in[6];
    float* out = (float*)d_out;

    cvt_w1_kernel<<<dim3(16, 8, 8), dim3(32, 8)>>>(W1);
    cvt_w2_kernel<<<dim3(8, 4, 8), dim3(32, 8)>>>(W2);

    cudaFuncSetAttribute(moe_fused_kernel,
                         cudaFuncAttributeMaxDynamicSharedMemorySize, SMEM_TOTAL);
    moe_fused_kernel<<<B_ROWS / M_TILE, THREADS, SMEM_TOTAL>>>(x, b1, b2, Wg, bg, out);
}